// round 3
// baseline (speedup 1.0000x reference)
#include <cuda_runtime.h>
#include <cuda_bf16.h>

// QFM: out[b] = sum_f linear_w[x[b,f]+f*V] + bias
//             + 0.5 * sum_d ( (sum_f emb[b,f,d])^2 - sum_f emb[b,f,d]^2 )
// emb[b,f, m*Q..] = codebooks[f*K + cb_index[x[b,f]+f*V][m], m*Q..(m+1)*Q)
// B=16384, F=39, V=100000, D=128, K=256, M=8, Q=16.

constexpr int F = 39;
constexpr int V = 100000;
constexpr int K = 256;
// D = 128 floats = 32 float4 per codebook row. Lane t owns float4 #t
// (dims 4t..4t+3), hence sub-codebook m = t>>2.

__global__ __launch_bounds__(256)
void qfm_kernel(const int*    __restrict__ x,          // (B, F)
                const float4* __restrict__ codebooks,  // (F*K, 32) as float4
                const int*    __restrict__ cb_index,   // (F*V, 8)
                const float*  __restrict__ linear_w,   // (F*V)
                const float*  __restrict__ linear_bias,// (1)
                float*        __restrict__ out,        // (B)
                int B)
{
    const int warp = (blockIdx.x * blockDim.x + threadIdx.x) >> 5;
    const int lane = threadIdx.x & 31;
    if (warp >= B) return;

    const int* xrow = x + warp * F;

    // Preload the 39 per-row indices into 2 registers (lanes 0..31, 0..6).
    const int idx_lo = xrow[lane];
    const int idx_hi = (lane < F - 32) ? xrow[32 + lane] : 0;

    // Linear term: one gather per lane (f = lane), plus 7 more on lanes 0..6.
    float lin = __ldg(&linear_w[lane * V + idx_lo]);
    if (lane < F - 32) lin += __ldg(&linear_w[(32 + lane) * V + idx_hi]);

    const int m = lane >> 2;

    float4 s = make_float4(0.f, 0.f, 0.f, 0.f);
    float4 q = make_float4(0.f, 0.f, 0.f, 0.f);

    #pragma unroll
    for (int f = 0; f < 32; ++f) {
        const int xo   = f * V + __shfl_sync(0xffffffffu, idx_lo, f);
        const int code = __ldg(&cb_index[xo * 8 + m]);
        const float4 e = __ldg(&codebooks[(f * K + code) * 32 + lane]);
        s.x += e.x; s.y += e.y; s.z += e.z; s.w += e.w;
        q.x = fmaf(e.x, e.x, q.x);
        q.y = fmaf(e.y, e.y, q.y);
        q.z = fmaf(e.z, e.z, q.z);
        q.w = fmaf(e.w, e.w, q.w);
    }
    #pragma unroll
    for (int f = 32; f < F; ++f) {
        const int xo   = f * V + __shfl_sync(0xffffffffu, idx_hi, f - 32);
        const int code = __ldg(&cb_index[xo * 8 + m]);
        const float4 e = __ldg(&codebooks[(f * K + code) * 32 + lane]);
        s.x += e.x; s.y += e.y; s.z += e.z; s.w += e.w;
        q.x = fmaf(e.x, e.x, q.x);
        q.y = fmaf(e.y, e.y, q.y);
        q.z = fmaf(e.z, e.z, q.z);
        q.w = fmaf(e.w, e.w, q.w);
    }

    // fm contribution of this lane's 4 dims.
    float t = 0.5f * ((fmaf(s.x, s.x, -q.x)) +
                      (fmaf(s.y, s.y, -q.y)) +
                      (fmaf(s.z, s.z, -q.z)) +
                      (fmaf(s.w, s.w, -q.w)));
    t += lin;

    #pragma unroll
    for (int o = 16; o > 0; o >>= 1)
        t += __shfl_xor_sync(0xffffffffu, t, o);

    if (lane == 0) out[warp] = t + __ldg(linear_bias);
}

extern "C" void kernel_launch(void* const* d_in, const int* in_sizes, int n_in,
                              void* d_out, int out_size)
{
    const int*    x         = (const int*)   d_in[0];
    const float4* codebooks = (const float4*)d_in[1];
    const int*    cb_index  = (const int*)   d_in[2];
    const float*  linear_w  = (const float*) d_in[3];
    const float*  lbias     = (const float*) d_in[4];
    float*        out       = (float*)       d_out;

    const int B = out_size;              // one output per row
    const int threads = 256;             // 8 warps/block, 1 warp per row
    const int blocks  = (B * 32 + threads - 1) / threads;
    qfm_kernel<<<blocks, threads>>>(x, codebooks, cb_index, linear_w, lbias, out, B);
}

// round 4
// speedup vs baseline: 1.1242x; 1.1242x over previous
#include <cuda_runtime.h>
#include <cuda_bf16.h>

// QFM: out[b] = sum_f linear_w[x[b,f]+f*V] + bias
//             + 0.5 * sum_d ( (sum_f emb[b,f,d])^2 - sum_f emb[b,f,d]^2 )
// emb[b,f, m*Q..] = codebooks[f*K + cb_index[x[b,f]+f*V][m], m*Q..(m+1)*Q)
// B=16384, F=39, V=100000, D=128, K=256, M=8, Q=16.
//
// One warp per row. Lane t owns float4 #t of the 512B codebook row
// (dims 4t..4t+3) -> sub-codebook m = t>>2.
//
// Structure (latency-optimized):
//   Phase A: 10 coalesced, mutually independent LDGs fetch all 39x8 codes
//            of this row into 10 regs/lane (chunk c, lane L holds
//            cb_index[xo_{4c+(L>>3)}*8 + (L&7)]).
//   Phase B: 39 iterations, each shfl(code) -> independent LDG.128 -> FMA.
//            No loop-carried loads => ptxas can batch gathers to the reg cap.

constexpr int F = 39;
constexpr int V = 100000;
constexpr int K = 256;

__global__ __launch_bounds__(256, 4)   // <=64 regs, 32 warps/SM
void qfm_kernel(const int*    __restrict__ x,          // (B, F)
                const float4* __restrict__ codebooks,  // (F*K, 32) as float4
                const int*    __restrict__ cb_index,   // (F*V, 8)
                const float*  __restrict__ linear_w,   // (F*V)
                const float*  __restrict__ linear_bias,// (1)
                float*        __restrict__ out,        // (B)
                int B)
{
    const unsigned FULL = 0xffffffffu;
    const int warp = (blockIdx.x * blockDim.x + threadIdx.x) >> 5;
    const int lane = threadIdx.x & 31;
    if (warp >= B) return;

    const int* xrow = x + warp * F;

    // Row indices: lanes 0..31 hold f=0..31, lanes 0..6 hold f=32..38.
    const int idx_lo = __ldcs(&xrow[lane]);
    const int idx_hi = (lane < F - 32) ? __ldcs(&xrow[32 + lane]) : 0;

    // Linear term (streaming, no reuse).
    float lin = __ldcs(&linear_w[lane * V + idx_lo]);
    if (lane < F - 32) lin += __ldcs(&linear_w[(32 + lane) * V + idx_hi]);

    // -------- Phase A: gather all codes with 10 independent coalesced LDGs.
    // Chunk c covers features 4c..4c+3; lane L reads code m=(L&7) of
    // feature fl = 4c + (L>>3).
    int codes[10];
    const int sub = lane >> 3;   // which of the 4 features in the chunk
    const int mm  = lane & 7;    // which sub-codebook code
    #pragma unroll
    for (int c = 0; c < 10; ++c) {
        const int fl = 4 * c + sub;
        int idxf;
        if (c < 8) idxf = __shfl_sync(FULL, idx_lo, fl);
        else       idxf = __shfl_sync(FULL, idx_hi, fl - 32);
        codes[c] = 0;
        if (fl < F) {
            const long long xo = (long long)fl * V + idxf;
            codes[c] = __ldcs(&cb_index[xo * 8 + mm]);
        }
    }

    // -------- Phase B: 39 independent float4 gathers + FMA accumulation.
    const int m = lane >> 2;     // this lane's sub-codebook
    float4 s = make_float4(0.f, 0.f, 0.f, 0.f);
    float4 q = make_float4(0.f, 0.f, 0.f, 0.f);

    #pragma unroll
    for (int f = 0; f < F; ++f) {
        const int src  = ((f & 3) << 3) | m;            // lane holding code(f, m)
        const int code = __shfl_sync(FULL, codes[f >> 2], src);
        const float4 e = __ldg(&codebooks[(f * K + code) * 32 + lane]);
        s.x += e.x; s.y += e.y; s.z += e.z; s.w += e.w;
        q.x = fmaf(e.x, e.x, q.x);
        q.y = fmaf(e.y, e.y, q.y);
        q.z = fmaf(e.z, e.z, q.z);
        q.w = fmaf(e.w, e.w, q.w);
    }

    // fm contribution of this lane's 4 dims + linear part.
    float t = 0.5f * (fmaf(s.x, s.x, -q.x) +
                      fmaf(s.y, s.y, -q.y) +
                      fmaf(s.z, s.z, -q.z) +
                      fmaf(s.w, s.w, -q.w));
    t += lin;

    #pragma unroll
    for (int o = 16; o > 0; o >>= 1)
        t += __shfl_xor_sync(FULL, t, o);

    if (lane == 0) out[warp] = t + __ldg(linear_bias);
}

extern "C" void kernel_launch(void* const* d_in, const int* in_sizes, int n_in,
                              void* d_out, int out_size)
{
    const int*    x         = (const int*)   d_in[0];
    const float4* codebooks = (const float4*)d_in[1];
    const int*    cb_index  = (const int*)   d_in[2];
    const float*  linear_w  = (const float*) d_in[3];
    const float*  lbias     = (const float*) d_in[4];
    float*        out       = (float*)       d_out;

    const int B = out_size;
    const int threads = 256;                       // 8 warps/block, 1 warp/row
    const int blocks  = (B * 32 + threads - 1) / threads;
    qfm_kernel<<<blocks, threads>>>(x, codebooks, cb_index, linear_w, lbias, out, B);
}